// round 6
// baseline (speedup 1.0000x reference)
#include <cuda_runtime.h>

// DTree_84061099917446 — soft decision tree forward pass.
// N=262144 rows, F=32, depth 8, 255 nodes, 256 leaves, C=1.
//
// R6: occupancy fix. One row per thread (xa: 32 regs instead of 64) under
// __launch_bounds__(256,4) -> 64-reg budget -> 32 warps/SM (was 16). The
// fma-pipe work is unchanged (~82us floor); doubling resident warps hides
// the per-node EX2->RCP gate chain that capped issue at 35.6% in R5.
// Still: full compile-time tree unroll (literal node indices, branch-free),
// W pre-scaled by -log2(e), gate = EX2+FADD+RCP, depth-7 leaf-pair folding.

#define F_      32
#define NODES_  255
#define LEAVES_ 256
#define N_ROWS  262144
#define TPB     256
#define LOG2E_F 1.4426950408889634f

typedef unsigned long long u64;

// Prologue results (scratch via __device__ globals — no allocation).
__device__ float g_W[NODES_ * F_];   // -log2e * relu(fi)
__device__ u64   g_c2[NODES_];       // packed float2 (+log2e * c, 0)

// ---------------------------------------------------------------------------
// Prologue. c[n] = sum_f relu(fi)*sigmoid(fs) (unscaled W); store scaled W.
// ---------------------------------------------------------------------------
__global__ void prep_kernel(const float* __restrict__ fi,
                            const float* __restrict__ fs) {
    int n = blockIdx.x;          // node 0..254
    int f = threadIdx.x;         // feature 0..31
    int idx = n * F_ + f;
    float w = fmaxf(fi[idx], 0.0f);
    float s = 1.0f / (1.0f + expf(-fs[idx]));
    g_W[idx] = -LOG2E_F * w;
    float p = w * s;
    #pragma unroll
    for (int o = 16; o > 0; o >>= 1) p += __shfl_xor_sync(0xffffffffu, p, o);
    if (f == 0) {
        float2 v; v.x = LOG2E_F * p; v.y = 0.0f;
        g_c2[n] = *reinterpret_cast<u64*>(&v);
    }
}

// ---------------------------------------------------------------------------
// Packed f32x2 / gate helpers.
// ---------------------------------------------------------------------------
__device__ __forceinline__ u64 ffma2(u64 a, u64 b, u64 c) {
    u64 d;
    asm("fma.rn.f32x2 %0, %1, %2, %3;" : "=l"(d) : "l"(a), "l"(b), "l"(c));
    return d;
}

// horizontal sum of two packed f32x2 accumulators -> scalar
__device__ __forceinline__ float psum(u64 a, u64 b) {
    u64 s;
    asm("add.rn.f32x2 %0, %1, %2;" : "=l"(s) : "l"(a), "l"(b));
    float lo, hi;
    asm("mov.b64 {%0, %1}, %2;" : "=f"(lo), "=f"(hi) : "l"(s));
    return lo + hi;
}

// y = -log2e * z  ->  g = sigmoid(z) = 1 / (1 + 2^y)
__device__ __forceinline__ float fgate(float y) {
    float e, g;
    asm("ex2.approx.f32 %0, %1;" : "=f"(e) : "f"(y));
    float d = 1.0f + e;
    asm("rcp.approx.f32 %0, %1;" : "=f"(g) : "f"(d));
    return g;
}

// ---------------------------------------------------------------------------
// Compile-time-unrolled DFS, one row. NODE is a literal at every
// instantiation; the 8-deep prod "stack" materializes as live registers of
// the inlined recursion. Depth-7 nodes fold their two leaves:
// acc += prod * (clsR + g*(clsL - clsR)).
// ---------------------------------------------------------------------------
template<int DEPTH, int NODE>
__device__ __forceinline__ void subtree(const float*  __restrict__ sW,
                                        const u64*    __restrict__ sc2,
                                        const float2* __restrict__ spair,
                                        const u64 (&xa)[16],
                                        float prod, float& acc) {
    const ulonglong2* wp =
        reinterpret_cast<const ulonglong2*>(sW + NODE * F_);
    u64 A0 = sc2[NODE];                // init = (+log2e*c, 0)
    u64 A1 = 0ull;
    #pragma unroll
    for (int i = 0; i < 8; ++i) {
        ulonglong2 w = wp[i];          // LDS.128 broadcast
        A0 = ffma2(xa[2*i],   w.x, A0);
        A1 = ffma2(xa[2*i+1], w.y, A1);
    }
    float g = fgate(psum(A0, A1));

    if constexpr (DEPTH == 7) {
        float2 pr = spair[NODE - 127];           // (clsR, clsL - clsR)
        acc = fmaf(prod, fmaf(g, pr.y, pr.x), acc);
    } else {
        float r = fmaf(-prod, g, prod);          // prod*(1-g)
        subtree<DEPTH + 1, 2 * NODE + 1>(sW, sc2, spair, xa, prod * g, acc);
        subtree<DEPTH + 1, 2 * NODE + 2>(sW, sc2, spair, xa, r, acc);
    }
}

// ---------------------------------------------------------------------------
__global__ void __launch_bounds__(TPB, 4)
dtree_kernel(const float* __restrict__ x,
             const float* __restrict__ cls,
             float* __restrict__ out) {
    __shared__ __align__(16) float  sW[NODES_ * F_];   // 32640 B
    __shared__ u64    sc2[NODES_];
    __shared__ float2 spair[LEAVES_ / 2];

    for (int i = threadIdx.x; i < NODES_ * F_; i += TPB) sW[i] = g_W[i];
    if (threadIdx.x < NODES_) sc2[threadIdx.x] = g_c2[threadIdx.x];
    if (threadIdx.x < LEAVES_ / 2) {
        float l = cls[2 * threadIdx.x];
        float r = cls[2 * threadIdx.x + 1];
        spair[threadIdx.x] = make_float2(r, l - r);
    }
    __syncthreads();

    int row = blockIdx.x * TPB + threadIdx.x;

    // Row features as 16 packed f32x2 (feature pairs), 2x LDG.128.
    u64 xa[16];
    {
        const ulonglong2* pa =
            reinterpret_cast<const ulonglong2*>(x + (size_t)row * F_);
        #pragma unroll
        for (int i = 0; i < 8; ++i) {
            ulonglong2 v = pa[i];
            xa[2*i] = v.x; xa[2*i+1] = v.y;
        }
    }

    float acc = 0.0f;
    subtree<0, 0>(sW, sc2, spair, xa, 1.0f, acc);

    out[row] = acc;
}

// ---------------------------------------------------------------------------
extern "C" void kernel_launch(void* const* d_in, const int* in_sizes, int n_in,
                              void* d_out, int out_size) {
    const float* x   = (const float*)d_in[0];   // (N, 32)
    const float* fi  = (const float*)d_in[1];   // (255*32, 1)
    const float* fs  = (const float*)d_in[2];   // (255*32, 1)
    const float* cls = (const float*)d_in[3];   // (256, 1)
    float* out = (float*)d_out;                 // (N, 1) float32

    prep_kernel<<<NODES_, 32>>>(fi, fs);
    dtree_kernel<<<N_ROWS / TPB, TPB>>>(x, cls, out);
}